// round 5
// baseline (speedup 1.0000x reference)
#include <cuda_runtime.h>
#include <math.h>

// HMM forward, 511 serial steps. 16 clusters x 8 CTAs; cluster owns 4 batches,
// CTA owns 64-row slice of W (fp32, smem-resident). Per step:
//   mbar wait -> matvec (x already pushed into local smem by all 8 CTAs)
//   -> log epilogue -> exp with LAGGED shift s_{t+1}=M_{t-1} -> DSMEM push of
//   x slice + local max to all 8 CTAs -> remote mbarrier arrives (release).
// No L2 state, no barrier.cluster in the loop.

#define HH 512
#define VV 50257
#define BB 64
#define TT 512
#define NT 512

using ull = unsigned long long;
using u32 = unsigned int;

#define CLUSTER_SYNC() do { \
  asm volatile("barrier.cluster.arrive.aligned;" ::: "memory"); \
  asm volatile("barrier.cluster.wait.aligned;"   ::: "memory"); \
} while (0)

__device__ __forceinline__ ull ffma2(ull a, ull b, ull c) {
  ull d;
  asm("fma.rn.f32x2 %0, %1, %2, %3;" : "=l"(d) : "l"(a), "l"(b), "l"(c));
  return d;
}
__device__ __forceinline__ float psum2(ull u) {
  return __uint_as_float((unsigned)u) + __uint_as_float((unsigned)(u >> 32));
}
__device__ __forceinline__ u32 smem_u32(const void* p) {
  u32 a;
  asm("{ .reg .u64 t; cvta.to.shared.u64 t, %1; cvt.u32.u64 %0, t; }" : "=r"(a) : "l"(p));
  return a;
}
__device__ __forceinline__ u32 mapa_u32(u32 local, int rank) {
  u32 r;
  asm("mapa.shared::cluster.u32 %0, %1, %2;" : "=r"(r) : "r"(local), "r"(rank));
  return r;
}
__device__ __forceinline__ void mbar_wait_acq(u32 addr, u32 ph) {
  asm volatile(
    "{\n\t.reg .pred P;\n\t"
    "W%=:\n\t"
    "mbarrier.try_wait.parity.acquire.cluster.shared::cta.b64 P, [%0], %1, 0x989680;\n\t"
    "@!P bra W%=;\n\t}"
    :: "r"(addr), "r"(ph) : "memory");
}

extern __shared__ float sW[];   // 128KB: W pairs [kp:256][r:64][2]

__global__ void __cluster_dims__(8, 1, 1) __launch_bounds__(NT, 1)
hmm_main(const float* __restrict__ A, const float* __restrict__ beta,
         const float* __restrict__ gamma, const int* __restrict__ ids,
         float* __restrict__ out) {
  __shared__ __align__(16) float2 xs[2][256][4];   // [parity][kp][b]
  __shared__ __align__(16) float4 red[16 * 64];
  __shared__ int    sids[4][TT];
  __shared__ float  swmax[64];
  __shared__ float  sAinv[64];
  __shared__ float  smax2[16];
  __shared__ float  smaxp[2][8][4];                // pushed per-CTA maxes
  __shared__ __align__(8) ull mbar;

  const int tid  = threadIdx.x;
  const int myq  = blockIdx.x & 7;     // cluster cta rank == row slice
  const int bg   = blockIdx.x >> 3;    // batch group
  const int base = myq * 64;
  const int warp = tid >> 5, lane = tid & 31;

  // ---- prologue: colmax of A's slice columns -> W into smem ----
  {
    float* pm = (float*)red;
    int qq = tid >> 6, c = tid & 63;
    float m = 0.0f;
    for (int j = qq; j < HH; j += 8) m = fmaxf(m, A[j * HH + base + c]);
    pm[qq * 64 + c] = m;
    __syncthreads();
    if (tid < 64) {
      float mm = pm[tid];
      #pragma unroll
      for (int q2 = 1; q2 < 8; q2++) mm = fmaxf(mm, pm[q2 * 64 + tid]);
      float d = mm + 1e-12f;
      sAinv[tid] = 1.0f / d;
      swmax[tid] = logf(d);
    }
    __syncthreads();
    for (int idx = tid; idx < 64 * HH; idx += NT) {
      int c2 = idx & 63, j = idx >> 6;
      float v = (A[j * HH + base + c2] + 1e-12f) * sAinv[c2];
      sW[(j >> 1) * 128 + c2 * 2 + (j & 1)] = v;
    }
    for (int i = tid; i < 4 * TT; i += NT) {
      int b0 = i >> 9, t0 = i & (TT - 1);
      sids[b0][t0] = ids[(bg * 4 + b0) * TT + t0];
    }
    if (tid == 0)
      asm volatile("mbarrier.init.shared.b64 [%0], %1;"
                   :: "r"(smem_u32(&mbar)), "r"(8u) : "memory");
  }
  __syncthreads();

  // ---- init: every CTA computes FULL alpha0, exact M0, and x_1 locally ----
  float M0[4];
  {
    float* a0s = (float*)red;            // 2048 floats
    for (int idx = tid; idx < 4 * HH; idx += NT) {
      int bb = idx >> 9, k = idx & 511;
      a0s[idx] = __logf(gamma[k]) + __ldg(&beta[(size_t)k * VV + sids[bb][0]]);
    }
    __syncthreads();
    {
      int bb = warp >> 2, seg = warp & 3;
      float m = -3.4e38f;
      #pragma unroll
      for (int i = 0; i < 4; i++)
        m = fmaxf(m, a0s[bb * 512 + seg * 128 + i * 32 + lane]);
      #pragma unroll
      for (int o = 16; o > 0; o >>= 1)
        m = fmaxf(m, __shfl_xor_sync(0xffffffffu, m, o));
      if (lane == 0) smax2[warp] = m;
    }
    __syncthreads();
    #pragma unroll
    for (int bb = 0; bb < 4; bb++)
      M0[bb] = fmaxf(fmaxf(smax2[4 * bb], smax2[4 * bb + 1]),
                     fmaxf(smax2[4 * bb + 2], smax2[4 * bb + 3]));
    for (int idx = tid; idx < 4 * HH; idx += NT) {
      int bb = idx >> 9, k = idx & 511;
      ((float*)xs[1])[(k >> 1) * 8 + bb * 2 + (k & 1)] = __expf(a0s[idx] - M0[bb]);
    }
  }
  __syncthreads();
  CLUSTER_SYNC();   // one-time: mbar init + xs[1] visible everywhere

  const bool active = tid < 256;
  const int b     = (tid >> 6) & 3;
  const int r     = tid & 63;
  const int h     = base + r;
  const int bglob = bg * 4 + b;

  const u32 mbar_a = smem_u32(&mbar);
  const u32 xs_u   = smem_u32(xs);
  const u32 smp_u  = smem_u32(smaxp);

  float scur = M0[b];        // shift used to build x_t (t=1: exact M0)
  u32 wph = 0;

  for (int t = 1; t < TT; t++) {
    const int par = t & 1;

    // prefetch emission (independent of peers)
    float bsel = 0.0f, snew = 0.0f;
    if (active) bsel = __ldg(&beta[(size_t)h * VV + sids[b][t]]);

    if (t >= 2) { mbar_wait_acq(mbar_a, wph); wph ^= 1; }

    if (active) {
      if (t == 1) snew = scur;          // s_2 = M_0 (exact)
      else {
        snew = smaxp[par][0][b];        // s_{t+1} = M_{t-1}
        #pragma unroll
        for (int q2 = 1; q2 < 8; q2++) snew = fmaxf(snew, smaxp[par][q2][b]);
      }
    }

    // ---- matvec on xs[par]: warp owns kp in [warp*16, warp*16+16) ----
    ull acc0 = 0, acc1 = 0, acc2 = 0, acc3 = 0,
        acc4 = 0, acc5 = 0, acc6 = 0, acc7 = 0;
    {
      const ull* wp = (const ull*)sW + warp * (16 * 64) + lane;
      const ulonglong2* xp =
          reinterpret_cast<const ulonglong2*>(&xs[par][0][0]) + warp * 32;
      #pragma unroll
      for (int kpi = 0; kpi < 16; kpi++) {
        ull w0 = wp[0];
        ull w1 = wp[32];
        ulonglong2 xa = xp[0];
        ulonglong2 xb = xp[1];
        wp += 64; xp += 2;
        acc0 = ffma2(w0, xa.x, acc0);
        acc1 = ffma2(w0, xa.y, acc1);
        acc2 = ffma2(w0, xb.x, acc2);
        acc3 = ffma2(w0, xb.y, acc3);
        acc4 = ffma2(w1, xa.x, acc4);
        acc5 = ffma2(w1, xa.y, acc5);
        acc6 = ffma2(w1, xb.x, acc6);
        acc7 = ffma2(w1, xb.y, acc7);
      }
    }
    red[warp * 64 + lane]      = make_float4(psum2(acc0), psum2(acc1), psum2(acc2), psum2(acc3));
    red[warp * 64 + lane + 32] = make_float4(psum2(acc4), psum2(acc5), psum2(acc6), psum2(acc7));
    __syncthreads();

    // ---- epilogue ----
    if (active) {
      const float* redf = (const float*)red;
      float z = 0.0f;
      #pragma unroll
      for (int w = 0; w < 16; w++) z += redf[(w * 64 + r) * 4 + b];
      float anew = __logf(z) + scur + swmax[r] + bsel;

      if (t == TT - 1) {
        out[bglob * HH + h] = anew;
      } else {
        // local max of anew over this warp (64-row batch max finished below)
        float lm = anew;
        #pragma unroll
        for (int o = 16; o > 0; o >>= 1)
          lm = fmaxf(lm, __shfl_xor_sync(0xffffffffu, lm, o));
        if (lane == 0) smax2[warp] = lm;

        // x_{t+1}, pushed to all 8 CTAs (8B lane-paired DSMEM stores)
        float v = __expf(anew - snew);
        float o2 = __shfl_xor_sync(0xffffffffu, v, 1);
        if (!(r & 1)) {
          u32 loc = xs_u + (u32)((((par ^ 1) * 256 + (h >> 1)) * 4 + b) * 8);
          #pragma unroll
          for (int q2 = 0; q2 < 8; q2++) {
            u32 ra = mapa_u32(loc, q2);
            asm volatile("st.shared::cluster.v2.f32 [%0], {%1, %2};"
                         :: "r"(ra), "f"(v), "f"(o2) : "memory");
          }
        }
      }
      scur = snew;
    }
    __syncthreads();   // all pushes + smax2 done

    if (t < TT - 1 && warp == 0) {
      if (lane < 4) {
        float m = fmaxf(smax2[2 * lane], smax2[2 * lane + 1]);
        u32 loc = smp_u + (u32)((((par ^ 1) * 8 + myq) * 4 + lane) * 4);
        #pragma unroll
        for (int q2 = 0; q2 < 8; q2++) {
          u32 ra = mapa_u32(loc, q2);
          asm volatile("st.shared::cluster.f32 [%0], %1;"
                       :: "r"(ra), "f"(m) : "memory");
        }
      }
      __syncwarp();
      if (lane == 0) {
        #pragma unroll
        for (int q2 = 0; q2 < 8; q2++) {
          u32 ra = mapa_u32(mbar_a, q2);
          asm volatile("mbarrier.arrive.release.cluster.shared::cluster.b64 _, [%0];"
                       :: "r"(ra) : "memory");
        }
      }
    }
  }
}

extern "C" void kernel_launch(void* const* d_in, const int* in_sizes, int n_in,
                              void* d_out, int out_size) {
  const float* A     = (const float*)d_in[0];   // alpha_exp (H,H)
  const float* beta  = (const float*)d_in[1];   // (H,V)
  const float* gamma = (const float*)d_in[2];   // (1,H)
  const int*   ids   = (const int*)d_in[3];     // (B,T) int32
  float* out = (float*)d_out;                   // (B,H) f32

  cudaFuncSetAttribute(hmm_main, cudaFuncAttributeMaxDynamicSharedMemorySize,
                       132 * 1024);
  hmm_main<<<128, NT, 131072>>>(A, beta, gamma, ids, out);
}

// round 6
// speedup vs baseline: 1.4400x; 1.4400x over previous
#include <cuda_runtime.h>
#include <math.h>

// HMM forward, linear-domain with lagged rescale. 16 clusters x 8 CTAs.
// CTA = 2 independent engines (warps 0-7, 8-15); engine owns 2 batches.
// CTA owns 64-row slice of W = A^T + eps (fp32, smem, shared by engines).
// Per engine-step: mbar wait -> copy x (L2, per-warp region) -> matvec ->
// named bar -> epilogue: u=z*e, x'=u*rcp(d), maxes; stcg -> named bar ->
// parallel remote arrives. C += log(d); out = log(u_T) + C.

#define HH 512
#define VV 50257
#define TT 512
#define NT 512

using ull = unsigned long long;
using u32 = unsigned int;

#define CLUSTER_SYNC() do { \
  asm volatile("barrier.cluster.arrive.aligned;" ::: "memory"); \
  asm volatile("barrier.cluster.wait.aligned;"   ::: "memory"); \
} while (0)

__device__ float g_X[2][16][2][1024];     // [par][cluster][eng][kp*4+b*2+hi]
__device__ float g_Max[2][16][2][8][2];   // [par][cluster][eng][ctaRank][b]

__device__ __forceinline__ ull ffma2(ull a, ull b, ull c) {
  ull d;
  asm("fma.rn.f32x2 %0, %1, %2, %3;" : "=l"(d) : "l"(a), "l"(b), "l"(c));
  return d;
}
__device__ __forceinline__ float psum2(ull u) {
  return __uint_as_float((unsigned)u) + __uint_as_float((unsigned)(u >> 32));
}
__device__ __forceinline__ u32 smem_u32(const void* p) {
  u32 a;
  asm("{ .reg .u64 t; cvta.to.shared.u64 t, %1; cvt.u32.u64 %0, t; }" : "=r"(a) : "l"(p));
  return a;
}
__device__ __forceinline__ u32 mapa_u32(u32 local, int rank) {
  u32 r;
  asm("mapa.shared::cluster.u32 %0, %1, %2;" : "=r"(r) : "r"(local), "r"(rank));
  return r;
}
__device__ __forceinline__ void mbar_wait_acq(u32 addr, u32 ph) {
  asm volatile(
    "{\n\t.reg .pred P;\n\t"
    "W%=:\n\t"
    "mbarrier.try_wait.parity.acquire.cluster.shared::cta.b64 P, [%0], %1, 0x989680;\n\t"
    "@!P bra W%=;\n\t}"
    :: "r"(addr), "r"(ph) : "memory");
}

extern __shared__ float sW[];   // 128KB: W pairs [kp:256][row:64][2]

__global__ void __cluster_dims__(8, 1, 1) __launch_bounds__(NT, 1)
hmm_main(const float* __restrict__ A, const float* __restrict__ beta,
         const float* __restrict__ gamma, const int* __restrict__ ids,
         float* __restrict__ out) {
  __shared__ __align__(16) float  xs[2][1024];   // [eng][kp*4+b*2+hi]
  __shared__ __align__(16) float2 red[2][8][64]; // [eng][warp][row] (b0,b1)
  __shared__ int    sids[4][TT];
  __shared__ float  sm[2][4];                    // per-engine warp maxes
  __shared__ float  smax2[16];
  __shared__ __align__(8) ull mbars[2];

  const int tid  = threadIdx.x;
  const int myq  = blockIdx.x & 7;     // cluster cta rank == row slice
  const int cl   = blockIdx.x >> 3;    // cluster id == batch group
  const int base = myq * 64;
  const int warp = tid >> 5, lane = tid & 31;
  const int eng  = tid >> 8;           // engine 0/1
  const int te   = tid & 255;          // thread-in-engine
  const int we   = warp & 7;           // warp-in-engine

  // ---- prologue: W slice (no normalization needed in linear domain) ----
  for (int idx = tid; idx < 64 * HH; idx += NT) {
    int c = idx & 63, j = idx >> 6;
    sW[(j >> 1) * 128 + c * 2 + (j & 1)] = A[j * HH + base + c] + 1e-12f;
  }
  for (int i = tid; i < 4 * TT; i += NT) {
    int b0 = i >> 9, t0 = i & (TT - 1);
    sids[b0][t0] = ids[(cl * 4 + b0) * TT + t0];
  }
  if (tid == 0) {
    asm volatile("mbarrier.init.shared.b64 [%0], %1;"
                 :: "r"(smem_u32(&mbars[0])), "r"(8u) : "memory");
    asm volatile("mbarrier.init.shared.b64 [%0], %1;"
                 :: "r"(smem_u32(&mbars[1])), "r"(8u) : "memory");
  }
  __syncthreads();

  // ---- init: full alpha0 (4 batches), M0, x1 (rank 0 publishes) ----
  float M0[4];
  {
    float* a0s = (float*)red;            // 2048 floats
    for (int idx = tid; idx < 4 * HH; idx += NT) {
      int bb = idx >> 9, k = idx & 511;
      a0s[idx] = __logf(gamma[k]) + __ldg(&beta[(size_t)k * VV + sids[bb][0]]);
    }
    __syncthreads();
    {
      int bb = warp >> 2, seg = warp & 3;
      float m = -3.4e38f;
      #pragma unroll
      for (int i = 0; i < 4; i++)
        m = fmaxf(m, a0s[bb * 512 + seg * 128 + i * 32 + lane]);
      #pragma unroll
      for (int o = 16; o > 0; o >>= 1)
        m = fmaxf(m, __shfl_xor_sync(0xffffffffu, m, o));
      if (lane == 0) smax2[warp] = m;
    }
    __syncthreads();
    #pragma unroll
    for (int bb = 0; bb < 4; bb++)
      M0[bb] = fmaxf(fmaxf(smax2[4 * bb], smax2[4 * bb + 1]),
                     fmaxf(smax2[4 * bb + 2], smax2[4 * bb + 3]));
    if (myq == 0) {
      for (int idx = tid; idx < 4 * HH; idx += NT) {
        int bb = idx >> 9, k = idx & 511;
        float v = __expf(a0s[idx] - M0[bb]);
        __stcg(&g_X[1][cl][bb >> 1][(k >> 1) * 4 + (bb & 1) * 2 + (k & 1)], v);
      }
    }
    __syncthreads();   // a0s (== red) free before first matvec
  }
  CLUSTER_SYNC();      // x1 + mbar inits visible cluster-wide

  const bool act = (te < 128);
  const int  b_e = (te >> 6) & 1;      // batch-in-engine
  const int  r   = te & 63;
  const int  h   = base + r;
  float C = M0[eng * 2 + b_e];
  const u32 mbar_a = smem_u32(&mbars[eng]);
  float* const xse = xs[eng];
  u32 wph = 0;

  for (int t = 1; t < TT; t++) {
    const int par = t & 1;

    // prefetch emission logit (local data; exp taken late)
    float bsel = 0.0f;
    if (act) bsel = __ldg(&beta[(size_t)h * VV + sids[eng * 2 + b_e][t]]);

    float d = 1.0f;
    if (t >= 2) {
      mbar_wait_acq(mbar_a, wph);
      wph ^= 1;
      if (act) {
        const float* gm = &g_Max[par][cl][eng][0][b_e];
        d = __ldcg(&gm[0]);
        #pragma unroll
        for (int q = 1; q < 8; q++) d = fmaxf(d, __ldcg(&gm[q * 2]));
      }
    }

    // copy x: each warp copies exactly its own 512B region
    {
      const float4* src = (const float4*)&g_X[par][cl][eng][0];
      float4 v = __ldcg(src + we * 32 + lane);
      *(float4*)(xse + (we * 32 + lane) * 4) = v;
      __syncwarp();
    }

    // matvec: warp owns kp in [32*we, 32*we+32); rows {lane, lane+32} x 2 b
    ull a00 = 0, a01 = 0, a10 = 0, a11 = 0;
    {
      const ull* wp = (const ull*)sW + we * 2048 + lane;
      const ulonglong2* xp = (const ulonglong2*)xse + we * 32;
      #pragma unroll
      for (int kpi = 0; kpi < 32; kpi++) {
        ull w0 = wp[0];
        ull w1 = wp[32];
        ulonglong2 xv = xp[kpi];    // warp-uniform broadcast
        wp += 64;
        a00 = ffma2(w0, xv.x, a00);
        a01 = ffma2(w0, xv.y, a01);
        a10 = ffma2(w1, xv.x, a10);
        a11 = ffma2(w1, xv.y, a11);
      }
    }
    red[eng][we][lane]      = make_float2(psum2(a00), psum2(a01));
    red[eng][we][lane + 32] = make_float2(psum2(a10), psum2(a11));
    asm volatile("bar.sync %0, %1;" :: "r"(1 + eng), "r"(256) : "memory");

    if (act) {
      const float* rp = &red[eng][0][0].x + r * 2 + b_e;
      float z = rp[0];
      #pragma unroll
      for (int w = 1; w < 8; w++) z += rp[w * 128];
      float u = z * __expf(bsel);

      if (t == TT - 1) {
        out[(cl * 4 + eng * 2 + b_e) * HH + h] = __logf(u) + C;
      } else {
        __stcg(&g_X[par ^ 1][cl][eng][(h >> 1) * 4 + b_e * 2 + (h & 1)],
               u * __frcp_rn(d));
        float lm = u;
        #pragma unroll
        for (int o = 16; o > 0; o >>= 1)
          lm = fmaxf(lm, __shfl_xor_sync(0xffffffffu, lm, o));
        if (lane == 0) sm[eng][te >> 5] = lm;
        C += __logf(d);
      }
    }

    if (t < TT - 1) {
      asm volatile("bar.sync %0, %1;" :: "r"(1 + eng), "r"(256) : "memory");
      if (we == 0) {
        if (lane < 2)
          __stcg(&g_Max[par ^ 1][cl][eng][myq][lane],
                 fmaxf(sm[eng][lane * 2], sm[eng][lane * 2 + 1]));
        __syncwarp();
        if (lane < 8) {   // parallel remote arrives, one rank per lane
          u32 ra = mapa_u32(mbar_a, lane);
          asm volatile("mbarrier.arrive.release.cluster.shared::cluster.b64 _, [%0];"
                       :: "r"(ra) : "memory");
        }
      }
    }
  }
}

extern "C" void kernel_launch(void* const* d_in, const int* in_sizes, int n_in,
                              void* d_out, int out_size) {
  const float* A     = (const float*)d_in[0];   // alpha_exp (H,H)
  const float* beta  = (const float*)d_in[1];   // (H,V)
  const float* gamma = (const float*)d_in[2];   // (1,H)
  const int*   ids   = (const int*)d_in[3];     // (B,T) int32
  float* out = (float*)d_out;                   // (B,H) f32

  cudaFuncSetAttribute(hmm_main, cudaFuncAttributeMaxDynamicSharedMemorySize,
                       132 * 1024);
  hmm_main<<<128, NT, 131072>>>(A, beta, gamma, ids, out);
}